// round 12
// baseline (speedup 1.0000x reference)
#include <cuda_runtime.h>
#include <cstdint>

#define BATCH 4
#define SEQ   2048
#define DMODEL 1024

// Scratch (device globals — no cudaMalloc allowed)
__device__ float g_QKV[(size_t)3 * BATCH * SEQ * DMODEL];   // 96 MB (Q,K planes used)
__device__ float g_P  [(size_t)BATCH * SEQ * SEQ];          // 64 MB (exp-scores)
__device__ float g_AO [(size_t)BATCH * SEQ * DMODEL];       // 32 MB
__device__ float g_X  [(size_t)BATCH * SEQ * DMODEL];       // 32 MB (tf32-rounded x)
__device__ float g_W  [(size_t)4 * DMODEL * DMODEL];        // 16 MB (WqT,WkT,WvT,WoT rounded)
__device__ float g_VT [(size_t)BATCH * SEQ * DMODEL];       // 32 MB (V transposed per batch)
__device__ float g_RS [(size_t)BATCH * SEQ];                // 32 KB (1/rowsum)
__device__ int   g_MI;                                      // mask layout flag

__device__ __forceinline__ uint32_t f2tf32(float x) {
    uint32_t r;
    asm("cvt.rna.tf32.f32 %0, %1;" : "=r"(r) : "f"(x));
    return r;
}
__device__ __forceinline__ float rtf(float x) { return __uint_as_float(f2tf32(x)); }

__device__ __forceinline__ void mma8(float c[4], const uint32_t a[4], const uint32_t b[2]) {
    asm volatile(
        "mma.sync.aligned.m16n8k8.row.col.f32.tf32.tf32.f32 "
        "{%0,%1,%2,%3}, {%4,%5,%6,%7}, {%8,%9}, {%0,%1,%2,%3};\n"
        : "+f"(c[0]), "+f"(c[1]), "+f"(c[2]), "+f"(c[3])
        : "r"(a[0]), "r"(a[1]), "r"(a[2]), "r"(a[3]), "r"(b[0]), "r"(b[1]));
}

__device__ __forceinline__ void cpa16s(uint32_t dst, const float* src) {
    asm volatile("cp.async.cg.shared.global [%0], [%1], 16;\n" :: "r"(dst), "l"(src));
}

__device__ __forceinline__ void ldmx4s(uint32_t r[4], uint32_t addr) {
    asm volatile("ldmatrix.sync.aligned.m8n8.x4.shared.b16 {%0,%1,%2,%3}, [%4];"
        : "=r"(r[0]), "=r"(r[1]), "=r"(r[2]), "=r"(r[3]) : "r"(addr));
}

// SW128-style XOR swizzle on byte offsets (16B granular)
__device__ __forceinline__ uint32_t sw128(uint32_t off) {
    return off ^ ((off >> 3) & 0x70u);
}

// ---------------- pre-pass kernels ----------------

__global__ void round_tf32(const float4* __restrict__ in, float4* __restrict__ out, int n4)
{
    int i = blockIdx.x * blockDim.x + threadIdx.x;
    if (i < n4) {
        float4 v = in[i];
        v.x = rtf(v.x); v.y = rtf(v.y); v.z = rtf(v.z); v.w = rtf(v.w);
        out[i] = v;
    }
}

// Fused 4-weight transpose+round: z selects source W; out plane z.
// Also probes mask layout once (block (0,0,z=0), thread 0) -> g_MI.
__global__ void transpose_round_w(const float* __restrict__ W0, const float* __restrict__ W1,
                                  const float* __restrict__ W2, const float* __restrict__ W3,
                                  float* __restrict__ out,
                                  const unsigned char* __restrict__ mask)
{
    __shared__ float tile[32][33];
    const int z = blockIdx.z;
    const int tx = threadIdx.x, ty = threadIdx.y;
    if (z == 0 && blockIdx.x == 0 && blockIdx.y == 0 && tx == 0 && ty == 0) {
        int ii = 1;
        for (int i = 0; i < 256; i++)
            if ((i & 3) != 0 && mask[i] != 0) ii = 0;
        g_MI = ii;
    }
    const float* in = (z == 0) ? W0 : (z == 1) ? W1 : (z == 2) ? W2 : W3;
    out += (size_t)z * DMODEL * DMODEL;
    const int bx = blockIdx.x * 32;
    const int by = blockIdx.y * 32;
    #pragma unroll
    for (int i = 0; i < 32; i += 8)
        tile[ty + i][tx] = in[(size_t)(by + ty + i) * DMODEL + bx + tx];
    __syncthreads();
    #pragma unroll
    for (int i = 0; i < 32; i += 8)
        out[(size_t)(bx + ty + i) * DMODEL + by + tx] = rtf(tile[tx][ty + i]);
}

// ---------------- NT TF32 GEMM: C[M,N] = A[M,K] * B[N,K]^T ----------------
// CTA tile 128x128x32, 4 warps (2x2), warp tile 64x64, 3-stage cp.async,
// XOR-swizzled smem, ldmatrix fragments (register double-buffered).
//   TRIPLE: blockIdx.z selects B among {B0,B1,B2}; z==2 writes transposed to vt.
//   DORS: accumulate A row sums in mainloop; CTA x==0 writes 1/rowsum to rsOut.
//   mask: epilogue exp(v*scale) masked->0, tf32-rounded (scores path)
//   rowinv: multiply row r by rowinv[bz*M+r] (out-projection path)
//   roundC: round outputs to tf32.
template<bool TRIPLE, bool DORS>
__global__ __launch_bounds__(128, 2)
void gemm_nt(const float* __restrict__ A, const float* __restrict__ B0,
             const float* __restrict__ B1, const float* __restrict__ B2,
             float* __restrict__ C, int M, int N, int K,
             size_t sA, size_t sB, size_t sC,
             const unsigned char* __restrict__ mask, float scale, int roundC,
             const float* __restrict__ rowinv, float* __restrict__ vt,
             float* __restrict__ rsOut)
{
    constexpr int BK = 32;
    constexpr uint32_t TILE_B = 128u * 128u;     // 16 KB per operand tile
    constexpr uint32_t STG_B  = 2u * TILE_B;     // 32 KB per stage
    constexpr int NSTAGE = 3;

    extern __shared__ float smf[];

    const int bz = blockIdx.z;
    const float* B;
    if (TRIPLE) {
        B = (bz == 0) ? B0 : (bz == 1 ? B1 : B2);
        C += (size_t)bz * sC;
    } else {
        B = B0 + (size_t)bz * sB;
        A += (size_t)bz * sA;
        C += (size_t)bz * sC;
    }

    const int bm = blockIdx.y * 128;
    const int bn = blockIdx.x * 128;
    const int t    = threadIdx.x;
    const int lane = t & 31;
    const int wid  = t >> 5;
    const int wm   = wid >> 1;        // 0..1 (M)
    const int wn   = wid & 1;         // 0..1 (N)
    const int g    = lane >> 2;       // 0..7
    const int tig  = lane & 3;        // 0..3

    uint32_t smem_base = (uint32_t)__cvta_generic_to_shared(smf);
    smem_base = (smem_base + 127u) & ~127u;

    float acc[4][8][4];
    #pragma unroll
    for (int i = 0; i < 4; i++)
        #pragma unroll
        for (int j = 0; j < 8; j++)
            #pragma unroll
            for (int r = 0; r < 4; r++) acc[i][j][r] = 0.f;

    float rs[4][2];
    if (DORS) {
        #pragma unroll
        for (int i = 0; i < 4; i++) { rs[i][0] = 0.f; rs[i][1] = 0.f; }
    }

    const int nkt = K / BK;

    auto issue = [&](int kt) {
        const uint32_t abase = smem_base + (uint32_t)(kt % NSTAGE) * STG_B;
        const uint32_t bbase = abase + TILE_B;
        const float* gA = A + (size_t)bm * K + (size_t)kt * BK;
        const float* gB = B + (size_t)bn * K + (size_t)kt * BK;
        #pragma unroll
        for (int i = 0; i < 8; i++) {
            const int chunk = t + i * 128;          // 0..1023
            const int row = chunk >> 3, kc = chunk & 7;
            const uint32_t sw = sw128((uint32_t)(row * 128 + kc * 16));
            cpa16s(abase + sw, gA + (size_t)row * K + kc * 4);
            cpa16s(bbase + sw, gB + (size_t)row * K + kc * 4);
        }
        asm volatile("cp.async.commit_group;\n");
    };

    issue(0); issue(1);

    const int a_row = (lane & 15);
    const int a_kof = (lane >> 4) << 2;
    const int b_row = (lane & 7) + ((lane & 16) >> 1);
    const int b_kof = (lane & 8) >> 1;

    uint32_t af[2][4][4];
    uint32_t bf[2][8][2];

    for (int kt = 0; kt < nkt; ++kt) {
        if (kt + 1 < nkt) asm volatile("cp.async.wait_group 1;\n");
        else              asm volatile("cp.async.wait_group 0;\n");
        __syncthreads();

        const uint32_t abase = smem_base + (uint32_t)(kt % NSTAGE) * STG_B;
        const uint32_t bbase = abase + TILE_B;

        auto ldfrag = [&](int ks, int buf) {
            const int k0 = ks * 8;
            #pragma unroll
            for (int i = 0; i < 4; i++) {
                const int rb = wm * 64 + i * 16;
                const uint32_t off = (uint32_t)((rb + a_row) * 128 + (k0 + a_kof) * 4);
                ldmx4s(af[buf][i], abase + sw128(off));
            }
            if (DORS) {
                #pragma unroll
                for (int i = 0; i < 4; i++) {
                    rs[i][0] += __uint_as_float(af[buf][i][0]) + __uint_as_float(af[buf][i][2]);
                    rs[i][1] += __uint_as_float(af[buf][i][1]) + __uint_as_float(af[buf][i][3]);
                }
            }
            #pragma unroll
            for (int jp = 0; jp < 4; jp++) {
                uint32_t bq[4];
                const int nb = wn * 64 + jp * 16;
                const uint32_t off = (uint32_t)((nb + b_row) * 128 + (k0 + b_kof) * 4);
                ldmx4s(bq, bbase + sw128(off));
                bf[buf][jp * 2][0]     = bq[0];
                bf[buf][jp * 2][1]     = bq[1];
                bf[buf][jp * 2 + 1][0] = bq[2];
                bf[buf][jp * 2 + 1][1] = bq[3];
            }
        };

        ldfrag(0, 0);
        if (kt + 2 < nkt) issue(kt + 2);

        #pragma unroll
        for (int ks = 0; ks < 4; ++ks) {
            const int cur = ks & 1;
            if (ks < 3) ldfrag(ks + 1, cur ^ 1);
            #pragma unroll
            for (int i = 0; i < 4; i++)
                #pragma unroll
                for (int j = 0; j < 8; j++)
                    mma8(acc[i][j], af[cur][i], bf[cur][j]);
        }
    }

    // ---- rowsum output (PV path): CTA x==0, warps with wn==0 ----
    if (DORS && blockIdx.x == 0 && wn == 0) {
        #pragma unroll
        for (int i = 0; i < 4; i++) {
            #pragma unroll
            for (int h = 0; h < 2; h++) {
                float s = rs[i][h];
                s += __shfl_xor_sync(0xffffffffu, s, 1);
                s += __shfl_xor_sync(0xffffffffu, s, 2);
                if (tig == 0)
                    rsOut[(size_t)bz * M + bm + wm * 64 + i * 16 + h * 8 + g] = 1.0f / s;
            }
        }
    }

    // ---- epilogue ----
    if (TRIPLE && bz == 2) {
        // V plane: write transposed (VT[b][d][s]) via smem staging; skip C store.
        __syncthreads();                 // all warps done reading stage smem
        float* ts = smf;                 // [128][129] row-major
        #pragma unroll
        for (int i = 0; i < 4; i++) {
            const int rl = wm * 64 + i * 16 + g;
            #pragma unroll
            for (int j = 0; j < 8; j++) {
                const int cl = wn * 64 + j * 8 + tig * 2;
                ts[rl * 129 + cl]           = rtf(acc[i][j][0]);
                ts[rl * 129 + cl + 1]       = rtf(acc[i][j][1]);
                ts[(rl + 8) * 129 + cl]     = rtf(acc[i][j][2]);
                ts[(rl + 8) * 129 + cl + 1] = rtf(acc[i][j][3]);
            }
        }
        __syncthreads();
        const int b     = bm >> 11;          // bm / 2048
        const int sbase = bm & 2047;
        float* vtp = vt + (size_t)b * ((size_t)SEQ * DMODEL);
        #pragma unroll 4
        for (int i = 0; i < 32; i++) {
            const int c = wid * 32 + i;      // local d
            float* dstrow = vtp + (size_t)(bn + c) * SEQ + sbase;
            #pragma unroll
            for (int ch = 0; ch < 4; ch++) {
                const int s = lane + ch * 32;
                dstrow[s] = ts[s * 129 + c];
            }
        }
        return;
    }

    const int mask_int = mask ? g_MI : 0;

    #pragma unroll
    for (int i = 0; i < 4; i++) {
        const int r0 = bm + wm * 64 + i * 16 + g;
        float ri0 = 1.f, ri1 = 1.f;
        if (rowinv) {
            ri0 = rowinv[(size_t)bz * M + r0];
            ri1 = rowinv[(size_t)bz * M + r0 + 8];
        }
        #pragma unroll
        for (int j = 0; j < 8; j++) {
            const int c0 = bn + wn * 64 + j * 8 + tig * 2;
            float v0 = acc[i][j][0], v1 = acc[i][j][1];
            float v2 = acc[i][j][2], v3 = acc[i][j][3];
            if (mask) {
                // scores path: v -> exp(v*scale) (masked -> 0), tf32-rounded
                const size_t base = (size_t)bz * (size_t)M * N + (size_t)r0 * N;
                int m00, m01, m10, m11;
                if (mask_int) {
                    const int* mi = (const int*)mask;
                    int2 ma = *(const int2*)&mi[base + c0];
                    int2 mb = *(const int2*)&mi[base + (size_t)8 * N + c0];
                    m00 = ma.x; m01 = ma.y; m10 = mb.x; m11 = mb.y;
                } else {
                    m00 = mask[base + c0];                   m01 = mask[base + c0 + 1];
                    m10 = mask[base + (size_t)8 * N + c0];   m11 = mask[base + (size_t)8 * N + c0 + 1];
                }
                v0 = m00 ? rtf(__expf(v0 * scale)) : 0.f;
                v1 = m01 ? rtf(__expf(v1 * scale)) : 0.f;
                v2 = m10 ? rtf(__expf(v2 * scale)) : 0.f;
                v3 = m11 ? rtf(__expf(v3 * scale)) : 0.f;
            } else {
                if (rowinv) { v0 *= ri0; v1 *= ri0; v2 *= ri1; v3 *= ri1; }
                if (roundC) { v0 = rtf(v0); v1 = rtf(v1); v2 = rtf(v2); v3 = rtf(v3); }
            }
            float2 w0 = {v0, v1}, w1 = {v2, v3};
            *(float2*)&C[(size_t)r0 * N + c0]       = w0;
            *(float2*)&C[(size_t)(r0 + 8) * N + c0] = w1;
        }
    }
}

// ---------------- host ----------------

extern "C" void kernel_launch(void* const* d_in, const int* in_sizes, int n_in,
                              void* d_out, int out_size)
{
    const float*         x    = (const float*)d_in[0];
    const unsigned char* mask = (const unsigned char*)d_in[1];
    const float*         Wq   = (const float*)d_in[2];
    const float*         Wk   = (const float*)d_in[3];
    const float*         Wv   = (const float*)d_in[4];
    const float*         Wo   = (const float*)d_in[5];
    float*               out  = (float*)d_out;

    float *QKV, *P, *AO, *X, *W, *VT, *RS;
    cudaGetSymbolAddress((void**)&QKV, g_QKV);
    cudaGetSymbolAddress((void**)&P,   g_P);
    cudaGetSymbolAddress((void**)&AO,  g_AO);
    cudaGetSymbolAddress((void**)&X,   g_X);
    cudaGetSymbolAddress((void**)&W,   g_W);
    cudaGetSymbolAddress((void**)&VT,  g_VT);
    cudaGetSymbolAddress((void**)&RS,  g_RS);

    const size_t pstride = (size_t)BATCH * SEQ * DMODEL;   // full Q/K/V plane
    const size_t bstride = (size_t)SEQ * DMODEL;           // per-batch plane
    const size_t wsz = (size_t)DMODEL * DMODEL;
    float* WqT = W;
    float* WkT = W + wsz;
    float* WvT = W + 2 * wsz;
    float* Q  = QKV;
    float* Kp = QKV + pstride;
    float* WoT = W + 3 * wsz;

    // --- pre-pass: round x; fused transpose+round of all weights (+mask probe) ---
    {
        const int xe4 = (int)(pstride / 4);
        round_tf32<<<(xe4 + 255) / 256, 256>>>((const float4*)x, (float4*)X, xe4);
        dim3 tb(32, 8);
        dim3 tgw(DMODEL / 32, DMODEL / 32, 4);
        transpose_round_w<<<tgw, tb>>>(Wq, Wk, Wv, Wo, W, mask);
    }

    const int smemB = 3 * 32768 + 128;   // 3 stages + alignment slack
    cudaFuncSetAttribute(gemm_nt<true,  false>,
                         cudaFuncAttributeMaxDynamicSharedMemorySize, smemB);
    cudaFuncSetAttribute(gemm_nt<false, false>,
                         cudaFuncAttributeMaxDynamicSharedMemorySize, smemB);
    cudaFuncSetAttribute(gemm_nt<false, true>,
                         cudaFuncAttributeMaxDynamicSharedMemorySize, smemB);

    const int MS = BATCH * SEQ;   // 8192
    dim3 blk(128);

    // QKV projections fused: z in {Q,K,V}; V written transposed into VT
    dim3 gq(DMODEL / 128, MS / 128, 3);
    gemm_nt<true, false><<<gq, blk, smemB>>>(
        X, WqT, WkT, WvT, QKV, MS, DMODEL, DMODEL, 0, 0, pstride,
        nullptr, 1.f, 1, nullptr, VT, nullptr);

    // P = exp(Q K^T / 32) masked->0 (tf32-rounded)
    dim3 gs(SEQ / 128, SEQ / 128, BATCH);
    gemm_nt<false, false><<<gs, blk, smemB>>>(
        Q, Kp, nullptr, nullptr, P, SEQ, SEQ, DMODEL,
        bstride, bstride, (size_t)SEQ * SEQ, mask, 0.03125f, 0, nullptr, nullptr, nullptr);

    // AOu = P V (unnormalized, rounded); rowsums computed in-mainloop -> RS
    dim3 gv(DMODEL / 128, SEQ / 128, BATCH);
    gemm_nt<false, true><<<gv, blk, smemB>>>(
        P, VT, nullptr, nullptr, AO, SEQ, DMODEL, SEQ,
        (size_t)SEQ * SEQ, bstride, bstride, nullptr, 1.f, 1, nullptr, nullptr, RS);

    // out[m,n] = (AOu[m,k] * WoT[n,k]) * rowinv[m]
    dim3 go(DMODEL / 128, MS / 128, 1);
    gemm_nt<false, false><<<go, blk, smemB>>>(
        AO, WoT, nullptr, nullptr, out, MS, DMODEL, DMODEL, 0, 0, 0,
        nullptr, 1.f, 0, RS, nullptr, nullptr);
}

// round 13
// speedup vs baseline: 1.5575x; 1.5575x over previous
#include <cuda_runtime.h>
#include <cstdint>

#define BATCH 4
#define SEQ   2048
#define DMODEL 1024

// Scratch (device globals — no cudaMalloc allowed)
__device__ float g_QKV[(size_t)3 * BATCH * SEQ * DMODEL];   // 96 MB (Q,K planes used)
__device__ float g_P  [(size_t)BATCH * SEQ * SEQ];          // 64 MB (scores/probs)
__device__ float g_AO [(size_t)BATCH * SEQ * DMODEL];       // 32 MB
__device__ float g_X  [(size_t)BATCH * SEQ * DMODEL];       // 32 MB (tf32-rounded x)
__device__ float g_W  [(size_t)4 * DMODEL * DMODEL];        // 16 MB (WqT,WkT,WvT,WoT rounded)
__device__ float g_VT [(size_t)BATCH * SEQ * DMODEL];       // 32 MB (V transposed per batch)

__device__ __forceinline__ uint32_t f2tf32(float x) {
    uint32_t r;
    asm("cvt.rna.tf32.f32 %0, %1;" : "=r"(r) : "f"(x));
    return r;
}
__device__ __forceinline__ float rtf(float x) { return __uint_as_float(f2tf32(x)); }

__device__ __forceinline__ void mma8(float c[4], const uint32_t a[4], const uint32_t b[2]) {
    asm volatile(
        "mma.sync.aligned.m16n8k8.row.col.f32.tf32.tf32.f32 "
        "{%0,%1,%2,%3}, {%4,%5,%6,%7}, {%8,%9}, {%0,%1,%2,%3};\n"
        : "+f"(c[0]), "+f"(c[1]), "+f"(c[2]), "+f"(c[3])
        : "r"(a[0]), "r"(a[1]), "r"(a[2]), "r"(a[3]), "r"(b[0]), "r"(b[1]));
}

__device__ __forceinline__ void cpa16s(uint32_t dst, const float* src) {
    asm volatile("cp.async.cg.shared.global [%0], [%1], 16;\n" :: "r"(dst), "l"(src));
}

__device__ __forceinline__ void ldmx4s(uint32_t r[4], uint32_t addr) {
    asm volatile("ldmatrix.sync.aligned.m8n8.x4.shared.b16 {%0,%1,%2,%3}, [%4];"
        : "=r"(r[0]), "=r"(r[1]), "=r"(r[2]), "=r"(r[3]) : "r"(addr));
}

// SW128-style XOR swizzle on byte offsets (16B granular)
__device__ __forceinline__ uint32_t sw128(uint32_t off) {
    return off ^ ((off >> 3) & 0x70u);
}

// ---------------- pre-pass kernels ----------------

__global__ void round_tf32(const float4* __restrict__ in, float4* __restrict__ out, int n4)
{
    int i = blockIdx.x * blockDim.x + threadIdx.x;
    if (i < n4) {
        float4 v = in[i];
        v.x = rtf(v.x); v.y = rtf(v.y); v.z = rtf(v.z); v.w = rtf(v.w);
        out[i] = v;
    }
}

// Fused 4-weight transpose+round: z selects source W; out plane z.
__global__ void transpose_round_w(const float* __restrict__ W0, const float* __restrict__ W1,
                                  const float* __restrict__ W2, const float* __restrict__ W3,
                                  float* __restrict__ out)
{
    __shared__ float tile[32][33];
    const int z = blockIdx.z;
    const float* in = (z == 0) ? W0 : (z == 1) ? W1 : (z == 2) ? W2 : W3;
    out += (size_t)z * DMODEL * DMODEL;
    const int bx = blockIdx.x * 32;
    const int by = blockIdx.y * 32;
    const int tx = threadIdx.x, ty = threadIdx.y;
    #pragma unroll
    for (int i = 0; i < 32; i += 8)
        tile[ty + i][tx] = in[(size_t)(by + ty + i) * DMODEL + bx + tx];
    __syncthreads();
    #pragma unroll
    for (int i = 0; i < 32; i += 8)
        out[(size_t)(bx + ty + i) * DMODEL + by + tx] = rtf(tile[tx][ty + i]);
}

// ---------------- NT TF32 GEMM: C[M,N] = A[M,K] * B[N,K]^T ----------------
// CTA tile 128x128x32, 4 warps (2x2), warp tile 64x64, 3-stage cp.async,
// XOR-swizzled smem, ldmatrix fragments (register double-buffered).
//   TRIPLE: blockIdx.z selects B among {B0,B1,B2}; z==2 writes transposed to vt.
//   mask: epilogue val*scale, masked -> -1e10 (int32 vs byte auto-probe)
//   roundC: round outputs to tf32.
template<bool TRIPLE>
__global__ __launch_bounds__(128, 2)
void gemm_nt(const float* __restrict__ A, const float* __restrict__ B0,
             const float* __restrict__ B1, const float* __restrict__ B2,
             float* __restrict__ C, int M, int N, int K,
             size_t sA, size_t sB, size_t sC,
             const unsigned char* __restrict__ mask, float scale, int roundC,
             float* __restrict__ vt)
{
    constexpr int BK = 32;
    constexpr uint32_t TILE_B = 128u * 128u;     // 16 KB per operand tile
    constexpr uint32_t STG_B  = 2u * TILE_B;     // 32 KB per stage
    constexpr int NSTAGE = 3;

    extern __shared__ float smf[];
    __shared__ int mask_is_int32;

    const int bz = blockIdx.z;
    const float* B;
    if (TRIPLE) {
        B = (bz == 0) ? B0 : (bz == 1 ? B1 : B2);
        C += (size_t)bz * sC;
    } else {
        B = B0 + (size_t)bz * sB;
        A += (size_t)bz * sA;
        C += (size_t)bz * sC;
    }

    const int bm = blockIdx.y * 128;
    const int bn = blockIdx.x * 128;
    const int t    = threadIdx.x;
    const int lane = t & 31;
    const int wid  = t >> 5;
    const int wm   = wid >> 1;        // 0..1 (M)
    const int wn   = wid & 1;         // 0..1 (N)
    const int g    = lane >> 2;       // 0..7
    const int tig  = lane & 3;        // 0..3

    uint32_t smem_base = (uint32_t)__cvta_generic_to_shared(smf);
    smem_base = (smem_base + 127u) & ~127u;

    if (mask && t == 0) {
        int is_int = 1;
        #pragma unroll 4
        for (int i = 0; i < 256; i++)
            if ((i & 3) != 0 && mask[i] != 0) is_int = 0;
        mask_is_int32 = is_int;
    }

    float acc[4][8][4];
    #pragma unroll
    for (int i = 0; i < 4; i++)
        #pragma unroll
        for (int j = 0; j < 8; j++)
            #pragma unroll
            for (int r = 0; r < 4; r++) acc[i][j][r] = 0.f;

    const int nkt = K / BK;

    auto issue = [&](int kt) {
        const uint32_t abase = smem_base + (uint32_t)(kt % NSTAGE) * STG_B;
        const uint32_t bbase = abase + TILE_B;
        const float* gA = A + (size_t)bm * K + (size_t)kt * BK;
        const float* gB = B + (size_t)bn * K + (size_t)kt * BK;
        #pragma unroll
        for (int i = 0; i < 8; i++) {
            const int chunk = t + i * 128;          // 0..1023
            const int row = chunk >> 3, kc = chunk & 7;
            const uint32_t sw = sw128((uint32_t)(row * 128 + kc * 16));
            cpa16s(abase + sw, gA + (size_t)row * K + kc * 4);
            cpa16s(bbase + sw, gB + (size_t)row * K + kc * 4);
        }
        asm volatile("cp.async.commit_group;\n");
    };

    issue(0); issue(1);

    const int a_row = (lane & 15);
    const int a_kof = (lane >> 4) << 2;
    const int b_row = (lane & 7) + ((lane & 16) >> 1);
    const int b_kof = (lane & 8) >> 1;

    uint32_t af[2][4][4];
    uint32_t bf[2][8][2];

    for (int kt = 0; kt < nkt; ++kt) {
        if (kt + 1 < nkt) asm volatile("cp.async.wait_group 1;\n");
        else              asm volatile("cp.async.wait_group 0;\n");
        __syncthreads();

        const uint32_t abase = smem_base + (uint32_t)(kt % NSTAGE) * STG_B;
        const uint32_t bbase = abase + TILE_B;

        auto ldfrag = [&](int ks, int buf) {
            const int k0 = ks * 8;
            #pragma unroll
            for (int i = 0; i < 4; i++) {
                const int rb = wm * 64 + i * 16;
                const uint32_t off = (uint32_t)((rb + a_row) * 128 + (k0 + a_kof) * 4);
                ldmx4s(af[buf][i], abase + sw128(off));
            }
            #pragma unroll
            for (int jp = 0; jp < 4; jp++) {
                uint32_t bq[4];
                const int nb = wn * 64 + jp * 16;
                const uint32_t off = (uint32_t)((nb + b_row) * 128 + (k0 + b_kof) * 4);
                ldmx4s(bq, bbase + sw128(off));
                bf[buf][jp * 2][0]     = bq[0];
                bf[buf][jp * 2][1]     = bq[1];
                bf[buf][jp * 2 + 1][0] = bq[2];
                bf[buf][jp * 2 + 1][1] = bq[3];
            }
        };

        ldfrag(0, 0);
        if (kt + 2 < nkt) issue(kt + 2);

        #pragma unroll
        for (int ks = 0; ks < 4; ++ks) {
            const int cur = ks & 1;
            if (ks < 3) ldfrag(ks + 1, cur ^ 1);
            #pragma unroll
            for (int i = 0; i < 4; i++)
                #pragma unroll
                for (int j = 0; j < 8; j++)
                    mma8(acc[i][j], af[cur][i], bf[cur][j]);
        }
    }

    // ---- epilogue ----
    if (TRIPLE && bz == 2) {
        // V plane: write transposed (VT[b][d][s]) via smem staging; skip C store.
        __syncthreads();                 // all warps done reading stage smem
        float* ts = smf;                 // [128][129] row-major
        #pragma unroll
        for (int i = 0; i < 4; i++) {
            const int rl = wm * 64 + i * 16 + g;
            #pragma unroll
            for (int j = 0; j < 8; j++) {
                const int cl = wn * 64 + j * 8 + tig * 2;
                ts[rl * 129 + cl]           = rtf(acc[i][j][0]);
                ts[rl * 129 + cl + 1]       = rtf(acc[i][j][1]);
                ts[(rl + 8) * 129 + cl]     = rtf(acc[i][j][2]);
                ts[(rl + 8) * 129 + cl + 1] = rtf(acc[i][j][3]);
            }
        }
        __syncthreads();
        const int b     = bm >> 11;          // bm / 2048
        const int sbase = bm & 2047;
        float* vtp = vt + (size_t)b * ((size_t)SEQ * DMODEL);
        #pragma unroll 4
        for (int i = 0; i < 32; i++) {
            const int c = wid * 32 + i;      // local d
            float* dstrow = vtp + (size_t)(bn + c) * SEQ + sbase;
            #pragma unroll
            for (int ch = 0; ch < 4; ch++) {
                const int s = lane + ch * 32;
                dstrow[s] = ts[s * 129 + c];
            }
        }
        return;
    }

    #pragma unroll
    for (int i = 0; i < 4; i++) {
        const int r0 = bm + wm * 64 + i * 16 + g;
        #pragma unroll
        for (int j = 0; j < 8; j++) {
            const int c0 = bn + wn * 64 + j * 8 + tig * 2;
            float v0 = acc[i][j][0], v1 = acc[i][j][1];
            float v2 = acc[i][j][2], v3 = acc[i][j][3];
            if (mask) {
                const size_t base = (size_t)bz * (size_t)M * N + (size_t)r0 * N;
                int m00, m01, m10, m11;
                if (mask_is_int32) {
                    const int* mi = (const int*)mask;
                    int2 ma = *(const int2*)&mi[base + c0];
                    int2 mb = *(const int2*)&mi[base + (size_t)8 * N + c0];
                    m00 = ma.x; m01 = ma.y; m10 = mb.x; m11 = mb.y;
                } else {
                    m00 = mask[base + c0];                   m01 = mask[base + c0 + 1];
                    m10 = mask[base + (size_t)8 * N + c0];   m11 = mask[base + (size_t)8 * N + c0 + 1];
                }
                v0 = m00 ? v0 * scale : -1e10f;
                v1 = m01 ? v1 * scale : -1e10f;
                v2 = m10 ? v2 * scale : -1e10f;
                v3 = m11 ? v3 * scale : -1e10f;
            }
            if (roundC) {
                v0 = rtf(v0); v1 = rtf(v1); v2 = rtf(v2); v3 = rtf(v3);
            }
            float2 w0 = {v0, v1}, w1 = {v2, v3};
            *(float2*)&C[(size_t)r0 * N + c0]       = w0;
            *(float2*)&C[(size_t)(r0 + 8) * N + c0] = w1;
        }
    }
}

// ---------------- softmax ----------------

__global__ void softmax2048(float* __restrict__ P)
{
    float* p = P + (size_t)blockIdx.x * 2048;
    const int t = threadIdx.x, lane = t & 31, wid = t >> 5;
    __shared__ float red[8];

    float4 v0 = ((const float4*)p)[t];
    float4 v1 = ((const float4*)p)[t + 256];

    float m = fmaxf(fmaxf(fmaxf(v0.x, v0.y), fmaxf(v0.z, v0.w)),
                    fmaxf(fmaxf(v1.x, v1.y), fmaxf(v1.z, v1.w)));
    #pragma unroll
    for (int o = 16; o; o >>= 1) m = fmaxf(m, __shfl_xor_sync(0xffffffffu, m, o));
    if (lane == 0) red[wid] = m;
    __syncthreads();
    float bm = red[0];
    #pragma unroll
    for (int w = 1; w < 8; w++) bm = fmaxf(bm, red[w]);
    __syncthreads();

    v0.x = __expf(v0.x - bm); v0.y = __expf(v0.y - bm);
    v0.z = __expf(v0.z - bm); v0.w = __expf(v0.w - bm);
    v1.x = __expf(v1.x - bm); v1.y = __expf(v1.y - bm);
    v1.z = __expf(v1.z - bm); v1.w = __expf(v1.w - bm);

    float s = v0.x + v0.y + v0.z + v0.w + v1.x + v1.y + v1.z + v1.w;
    #pragma unroll
    for (int o = 16; o; o >>= 1) s += __shfl_xor_sync(0xffffffffu, s, o);
    if (lane == 0) red[wid] = s;
    __syncthreads();
    float bs = red[0];
    #pragma unroll
    for (int w = 1; w < 8; w++) bs += red[w];

    const float inv = 1.f / bs;
    v0.x = rtf(v0.x * inv); v0.y = rtf(v0.y * inv);
    v0.z = rtf(v0.z * inv); v0.w = rtf(v0.w * inv);
    v1.x = rtf(v1.x * inv); v1.y = rtf(v1.y * inv);
    v1.z = rtf(v1.z * inv); v1.w = rtf(v1.w * inv);
    ((float4*)p)[t]       = v0;
    ((float4*)p)[t + 256] = v1;
}

// ---------------- host ----------------

extern "C" void kernel_launch(void* const* d_in, const int* in_sizes, int n_in,
                              void* d_out, int out_size)
{
    const float*         x    = (const float*)d_in[0];
    const unsigned char* mask = (const unsigned char*)d_in[1];
    const float*         Wq   = (const float*)d_in[2];
    const float*         Wk   = (const float*)d_in[3];
    const float*         Wv   = (const float*)d_in[4];
    const float*         Wo   = (const float*)d_in[5];
    float*               out  = (float*)d_out;

    float *QKV, *P, *AO, *X, *W, *VT;
    cudaGetSymbolAddress((void**)&QKV, g_QKV);
    cudaGetSymbolAddress((void**)&P,   g_P);
    cudaGetSymbolAddress((void**)&AO,  g_AO);
    cudaGetSymbolAddress((void**)&X,   g_X);
    cudaGetSymbolAddress((void**)&W,   g_W);
    cudaGetSymbolAddress((void**)&VT,  g_VT);

    const size_t pstride = (size_t)BATCH * SEQ * DMODEL;   // full Q/K/V plane
    const size_t bstride = (size_t)SEQ * DMODEL;           // per-batch plane
    const size_t wsz = (size_t)DMODEL * DMODEL;
    float* WqT = W;
    float* WkT = W + wsz;
    float* WvT = W + 2 * wsz;
    float* WoT = W + 3 * wsz;
    float* Q  = QKV;
    float* Kp = QKV + pstride;

    // --- pre-pass: round x; fused transpose+round of all weights ---
    {
        const int xe4 = (int)(pstride / 4);
        round_tf32<<<(xe4 + 255) / 256, 256>>>((const float4*)x, (float4*)X, xe4);
        dim3 tb(32, 8);
        dim3 tgw(DMODEL / 32, DMODEL / 32, 4);
        transpose_round_w<<<tgw, tb>>>(Wq, Wk, Wv, Wo, W);
    }

    const int smemB = 3 * 32768 + 128;   // 3 stages + alignment slack
    cudaFuncSetAttribute(gemm_nt<true>,
                         cudaFuncAttributeMaxDynamicSharedMemorySize, smemB);
    cudaFuncSetAttribute(gemm_nt<false>,
                         cudaFuncAttributeMaxDynamicSharedMemorySize, smemB);

    const int MS = BATCH * SEQ;   // 8192
    dim3 blk(128);

    // QKV projections fused: z in {Q,K,V}; V written transposed into VT
    dim3 gq(DMODEL / 128, MS / 128, 3);
    gemm_nt<true><<<gq, blk, smemB>>>(
        X, WqT, WkT, WvT, QKV, MS, DMODEL, DMODEL, 0, 0, pstride,
        nullptr, 1.f, 1, VT);

    // scores = Q K^T / 32, masked -> -1e10
    dim3 gs(SEQ / 128, SEQ / 128, BATCH);
    gemm_nt<false><<<gs, blk, smemB>>>(
        Q, Kp, nullptr, nullptr, P, SEQ, SEQ, DMODEL,
        bstride, bstride, (size_t)SEQ * SEQ, mask, 0.03125f, 0, nullptr);

    softmax2048<<<BATCH * SEQ, 256>>>(P);

    // attn_out = P V  (B = VT[b] is [DMODEL rows, SEQ cols] K-major)
    dim3 gv(DMODEL / 128, SEQ / 128, BATCH);
    gemm_nt<false><<<gv, blk, smemB>>>(
        P, VT, nullptr, nullptr, AO, SEQ, DMODEL, SEQ,
        (size_t)SEQ * SEQ, bstride, bstride, nullptr, 1.f, 1, nullptr);

    // output projection: out[m,n] = AO[m,k] * WoT[n,k]
    dim3 go(DMODEL / 128, MS / 128, 1);
    gemm_nt<false><<<go, blk, smemB>>>(
        AO, WoT, nullptr, nullptr, out, MS, DMODEL, DMODEL, 0, 0, 0,
        nullptr, 1.f, 0, nullptr);
}

// round 14
// speedup vs baseline: 2.6986x; 1.7327x over previous
#include <cuda_runtime.h>
#include <cuda_fp16.h>
#include <cstdint>

#define BATCH 4
#define SEQ   2048
#define DMODEL 1024

// Scratch (device globals — no cudaMalloc allowed)
__device__ __half g_QKV16[(size_t)3 * BATCH * SEQ * DMODEL];  // 48 MB (Q,K planes used)
__device__ float  g_P32 [(size_t)BATCH * SEQ * SEQ];          // 64 MB (raw scores)
__device__ __half g_P16 [(size_t)BATCH * SEQ * SEQ];          // 32 MB (softmax probs)
__device__ __half g_AO16[(size_t)BATCH * SEQ * DMODEL];       // 16 MB
__device__ __half g_X16 [(size_t)BATCH * SEQ * DMODEL];       // 16 MB (fp16 x)
__device__ __half g_W16 [(size_t)4 * DMODEL * DMODEL];        // 8 MB (WqT,WkT,WvT,WoT)
__device__ __half g_VT16[(size_t)BATCH * SEQ * DMODEL];       // 16 MB (V^T per batch)

__device__ __forceinline__ void mma16(float c[4], const uint32_t a[4], const uint32_t b[2]) {
    asm volatile(
        "mma.sync.aligned.m16n8k16.row.col.f32.f16.f16.f32 "
        "{%0,%1,%2,%3}, {%4,%5,%6,%7}, {%8,%9}, {%0,%1,%2,%3};\n"
        : "+f"(c[0]), "+f"(c[1]), "+f"(c[2]), "+f"(c[3])
        : "r"(a[0]), "r"(a[1]), "r"(a[2]), "r"(a[3]), "r"(b[0]), "r"(b[1]));
}

__device__ __forceinline__ void cpa16s(uint32_t dst, const void* src) {
    asm volatile("cp.async.cg.shared.global [%0], [%1], 16;\n" :: "r"(dst), "l"(src));
}

__device__ __forceinline__ void ldmx4s(uint32_t r[4], uint32_t addr) {
    asm volatile("ldmatrix.sync.aligned.m8n8.x4.shared.b16 {%0,%1,%2,%3}, [%4];"
        : "=r"(r[0]), "=r"(r[1]), "=r"(r[2]), "=r"(r[3]) : "r"(addr));
}

// SW128-style XOR swizzle on byte offsets (16B granular)
__device__ __forceinline__ uint32_t sw128(uint32_t off) {
    return off ^ ((off >> 3) & 0x70u);
}

// ---------------- pre-pass kernels ----------------

// fp32 -> fp16 conversion (4 elems/thread)
__global__ void to_half(const float4* __restrict__ in, __half* __restrict__ out, int n4)
{
    int i = blockIdx.x * blockDim.x + threadIdx.x;
    if (i < n4) {
        float4 v = in[i];
        __half2* o = (__half2*)(out + (size_t)i * 4);
        o[0] = __floats2half2_rn(v.x, v.y);
        o[1] = __floats2half2_rn(v.z, v.w);
    }
}

// Fused 4-weight transpose + fp16 convert: z selects source W; out plane z.
__global__ void transpose_w_h(const float* __restrict__ W0, const float* __restrict__ W1,
                              const float* __restrict__ W2, const float* __restrict__ W3,
                              __half* __restrict__ out)
{
    __shared__ float tile[32][33];
    const int z = blockIdx.z;
    const float* in = (z == 0) ? W0 : (z == 1) ? W1 : (z == 2) ? W2 : W3;
    out += (size_t)z * DMODEL * DMODEL;
    const int bx = blockIdx.x * 32;
    const int by = blockIdx.y * 32;
    const int tx = threadIdx.x, ty = threadIdx.y;
    #pragma unroll
    for (int i = 0; i < 32; i += 8)
        tile[ty + i][tx] = in[(size_t)(by + ty + i) * DMODEL + bx + tx];
    __syncthreads();
    #pragma unroll
    for (int i = 0; i < 32; i += 8)
        out[(size_t)(bx + ty + i) * DMODEL + by + tx] = __float2half_rn(tile[tx][ty + i]);
}

// ---------------- NT FP16 GEMM: C[M,N] = A[M,K] * B[N,K]^T ----------------
// CTA tile 128x128x64, 4 warps (2x2), warp tile 64x64, 3-stage cp.async,
// XOR-swizzled smem (128B rows of 64 halves), ldmatrix fragments (double-buffered),
// fp16 operands, fp32 accumulate.
//   TRIPLE: blockIdx.z selects B among {B0,B1,B2}; z==2 writes transposed to vt (fp16).
//   HALF_OUT: store C as fp16 (else fp32).
//   mask: epilogue val*scale, masked -> -1e10, fp32 C (scores path).
template<bool TRIPLE, bool HALF_OUT>
__global__ __launch_bounds__(128, 2)
void gemm_h(const __half* __restrict__ A, const __half* __restrict__ B0,
            const __half* __restrict__ B1, const __half* __restrict__ B2,
            void* __restrict__ Cv, int M, int N, int K,
            size_t sA, size_t sB, size_t sC,
            const unsigned char* __restrict__ mask, float scale,
            __half* __restrict__ vt)
{
    constexpr int BK = 64;                        // halves per K-tile (128 B rows)
    constexpr uint32_t TILE_B = 128u * 128u;      // 16 KB per operand tile
    constexpr uint32_t STG_B  = 2u * TILE_B;      // 32 KB per stage
    constexpr int NSTAGE = 3;

    extern __shared__ float smf[];
    __shared__ int mask_is_int32;

    const int bz = blockIdx.z;
    const __half* B;
    float*  C32 = (float*)Cv;
    __half* C16 = (__half*)Cv;
    if (TRIPLE) {
        B = (bz == 0) ? B0 : (bz == 1 ? B1 : B2);
        C16 += (size_t)bz * sC;
    } else {
        B = B0 + (size_t)bz * sB;
        A += (size_t)bz * sA;
        C32 += (size_t)bz * sC;
        C16 += (size_t)bz * sC;
    }

    const int bm = blockIdx.y * 128;
    const int bn = blockIdx.x * 128;
    const int t    = threadIdx.x;
    const int lane = t & 31;
    const int wid  = t >> 5;
    const int wm   = wid >> 1;        // 0..1 (M)
    const int wn   = wid & 1;         // 0..1 (N)
    const int g    = lane >> 2;       // 0..7
    const int tig  = lane & 3;        // 0..3

    uint32_t smem_base = (uint32_t)__cvta_generic_to_shared(smf);
    smem_base = (smem_base + 127u) & ~127u;

    if (mask && t == 0) {
        int is_int = 1;
        #pragma unroll 4
        for (int i = 0; i < 256; i++)
            if ((i & 3) != 0 && mask[i] != 0) is_int = 0;
        mask_is_int32 = is_int;
    }

    float acc[4][8][4];
    #pragma unroll
    for (int i = 0; i < 4; i++)
        #pragma unroll
        for (int j = 0; j < 8; j++)
            #pragma unroll
            for (int r = 0; r < 4; r++) acc[i][j][r] = 0.f;

    const int nkt = K / BK;

    auto issue = [&](int kt) {
        const uint32_t abase = smem_base + (uint32_t)(kt % NSTAGE) * STG_B;
        const uint32_t bbase = abase + TILE_B;
        const __half* gA = A + (size_t)bm * K + (size_t)kt * BK;
        const __half* gB = B + (size_t)bn * K + (size_t)kt * BK;
        #pragma unroll
        for (int i = 0; i < 8; i++) {
            const int chunk = t + i * 128;          // 0..1023
            const int row = chunk >> 3, kc = chunk & 7;   // 8 x 16B chunks per 128B row
            const uint32_t sw = sw128((uint32_t)(row * 128 + kc * 16));
            cpa16s(abase + sw, gA + (size_t)row * K + kc * 8);
            cpa16s(bbase + sw, gB + (size_t)row * K + kc * 8);
        }
        asm volatile("cp.async.commit_group;\n");
    };

    issue(0); issue(1);

    // ldmatrix per-lane selectors (byte offsets)
    const int a_row  = (lane & 15);
    const int a_kofb = (lane >> 4) << 4;                  // 0 or 16 bytes
    const int b_row  = (lane & 7) + ((lane & 16) >> 1);
    const int b_kofb = (lane & 8) << 1;                   // 0 or 16 bytes

    uint32_t af[2][4][4];
    uint32_t bf[2][8][2];

    for (int kt = 0; kt < nkt; ++kt) {
        if (kt + 1 < nkt) asm volatile("cp.async.wait_group 1;\n");
        else              asm volatile("cp.async.wait_group 0;\n");
        __syncthreads();

        const uint32_t abase = smem_base + (uint32_t)(kt % NSTAGE) * STG_B;
        const uint32_t bbase = abase + TILE_B;

        auto ldfrag = [&](int ks, int buf) {     // ks: k16 step within k64 tile
            const uint32_t kb = (uint32_t)ks * 32;   // 16 halves = 32 bytes
            #pragma unroll
            for (int i = 0; i < 4; i++) {
                const int rb = wm * 64 + i * 16;
                const uint32_t off = (uint32_t)((rb + a_row) * 128) + kb + a_kofb;
                ldmx4s(af[buf][i], abase + sw128(off));
            }
            #pragma unroll
            for (int jp = 0; jp < 4; jp++) {
                uint32_t bq[4];
                const int nb = wn * 64 + jp * 16;
                const uint32_t off = (uint32_t)((nb + b_row) * 128) + kb + b_kofb;
                ldmx4s(bq, bbase + sw128(off));
                bf[buf][jp * 2][0]     = bq[0];
                bf[buf][jp * 2][1]     = bq[1];
                bf[buf][jp * 2 + 1][0] = bq[2];
                bf[buf][jp * 2 + 1][1] = bq[3];
            }
        };

        ldfrag(0, 0);
        if (kt + 2 < nkt) issue(kt + 2);

        #pragma unroll
        for (int ks = 0; ks < 4; ++ks) {
            const int cur = ks & 1;
            if (ks < 3) ldfrag(ks + 1, cur ^ 1);
            #pragma unroll
            for (int i = 0; i < 4; i++)
                #pragma unroll
                for (int j = 0; j < 8; j++)
                    mma16(acc[i][j], af[cur][i], bf[cur][j]);
        }
    }

    // ---- epilogue ----
    if (TRIPLE && bz == 2) {
        // V plane: write transposed fp16 (VT[b][d][s]) via smem staging; skip C store.
        __syncthreads();
        float* ts = smf;                 // [128][129] floats (66KB <= 98KB smem)
        #pragma unroll
        for (int i = 0; i < 4; i++) {
            const int rl = wm * 64 + i * 16 + g;
            #pragma unroll
            for (int j = 0; j < 8; j++) {
                const int cl = wn * 64 + j * 8 + tig * 2;
                ts[rl * 129 + cl]           = acc[i][j][0];
                ts[rl * 129 + cl + 1]       = acc[i][j][1];
                ts[(rl + 8) * 129 + cl]     = acc[i][j][2];
                ts[(rl + 8) * 129 + cl + 1] = acc[i][j][3];
            }
        }
        __syncthreads();
        const int b     = bm >> 11;
        const int sbase = bm & 2047;
        __half* vtp = vt + (size_t)b * ((size_t)SEQ * DMODEL);
        #pragma unroll 4
        for (int i = 0; i < 32; i++) {
            const int c = wid * 32 + i;
            __half* dstrow = vtp + (size_t)(bn + c) * SEQ + sbase;
            #pragma unroll
            for (int ch = 0; ch < 4; ch++) {
                const int s = lane + ch * 32;
                dstrow[s] = __float2half_rn(ts[s * 129 + c]);
            }
        }
        return;
    }

    #pragma unroll
    for (int i = 0; i < 4; i++) {
        const int r0 = bm + wm * 64 + i * 16 + g;
        #pragma unroll
        for (int j = 0; j < 8; j++) {
            const int c0 = bn + wn * 64 + j * 8 + tig * 2;
            float v0 = acc[i][j][0], v1 = acc[i][j][1];
            float v2 = acc[i][j][2], v3 = acc[i][j][3];
            if (mask) {
                const size_t base = (size_t)bz * (size_t)M * N + (size_t)r0 * N;
                int m00, m01, m10, m11;
                if (mask_is_int32) {
                    const int* mi = (const int*)mask;
                    int2 ma = *(const int2*)&mi[base + c0];
                    int2 mb = *(const int2*)&mi[base + (size_t)8 * N + c0];
                    m00 = ma.x; m01 = ma.y; m10 = mb.x; m11 = mb.y;
                } else {
                    m00 = mask[base + c0];                   m01 = mask[base + c0 + 1];
                    m10 = mask[base + (size_t)8 * N + c0];   m11 = mask[base + (size_t)8 * N + c0 + 1];
                }
                v0 = m00 ? v0 * scale : -1e10f;
                v1 = m01 ? v1 * scale : -1e10f;
                v2 = m10 ? v2 * scale : -1e10f;
                v3 = m11 ? v3 * scale : -1e10f;
            }
            if (HALF_OUT) {
                *(__half2*)&C16[(size_t)r0 * N + c0]       = __floats2half2_rn(v0, v1);
                *(__half2*)&C16[(size_t)(r0 + 8) * N + c0] = __floats2half2_rn(v2, v3);
            } else {
                float2 w0 = {v0, v1}, w1 = {v2, v3};
                *(float2*)&C32[(size_t)r0 * N + c0]       = w0;
                *(float2*)&C32[(size_t)(r0 + 8) * N + c0] = w1;
            }
        }
    }
}

// ---------------- softmax: fp32 scores in, fp16 probs out ----------------

__global__ void softmax2048(const float* __restrict__ P32, __half* __restrict__ P16)
{
    const float* p = P32 + (size_t)blockIdx.x * 2048;
    __half* ph = P16 + (size_t)blockIdx.x * 2048;
    const int t = threadIdx.x, lane = t & 31, wid = t >> 5;
    __shared__ float red[8];

    float4 v0 = ((const float4*)p)[t];
    float4 v1 = ((const float4*)p)[t + 256];

    float m = fmaxf(fmaxf(fmaxf(v0.x, v0.y), fmaxf(v0.z, v0.w)),
                    fmaxf(fmaxf(v1.x, v1.y), fmaxf(v1.z, v1.w)));
    #pragma unroll
    for (int o = 16; o; o >>= 1) m = fmaxf(m, __shfl_xor_sync(0xffffffffu, m, o));
    if (lane == 0) red[wid] = m;
    __syncthreads();
    float bm = red[0];
    #pragma unroll
    for (int w = 1; w < 8; w++) bm = fmaxf(bm, red[w]);
    __syncthreads();

    v0.x = __expf(v0.x - bm); v0.y = __expf(v0.y - bm);
    v0.z = __expf(v0.z - bm); v0.w = __expf(v0.w - bm);
    v1.x = __expf(v1.x - bm); v1.y = __expf(v1.y - bm);
    v1.z = __expf(v1.z - bm); v1.w = __expf(v1.w - bm);

    float s = v0.x + v0.y + v0.z + v0.w + v1.x + v1.y + v1.z + v1.w;
    #pragma unroll
    for (int o = 16; o; o >>= 1) s += __shfl_xor_sync(0xffffffffu, s, o);
    if (lane == 0) red[wid] = s;
    __syncthreads();
    float bs = red[0];
    #pragma unroll
    for (int w = 1; w < 8; w++) bs += red[w];

    const float inv = 1.f / bs;
    __half2* o = (__half2*)ph;
    o[t * 2]             = __floats2half2_rn(v0.x * inv, v0.y * inv);
    o[t * 2 + 1]         = __floats2half2_rn(v0.z * inv, v0.w * inv);
    o[(t + 256) * 2]     = __floats2half2_rn(v1.x * inv, v1.y * inv);
    o[(t + 256) * 2 + 1] = __floats2half2_rn(v1.z * inv, v1.w * inv);
}

// ---------------- host ----------------

extern "C" void kernel_launch(void* const* d_in, const int* in_sizes, int n_in,
                              void* d_out, int out_size)
{
    const float*         x    = (const float*)d_in[0];
    const unsigned char* mask = (const unsigned char*)d_in[1];
    const float*         Wq   = (const float*)d_in[2];
    const float*         Wk   = (const float*)d_in[3];
    const float*         Wv   = (const float*)d_in[4];
    const float*         Wo   = (const float*)d_in[5];
    float*               out  = (float*)d_out;

    __half *QKV, *P16, *AO, *X, *W, *VT;
    float *P32;
    cudaGetSymbolAddress((void**)&QKV, g_QKV16);
    cudaGetSymbolAddress((void**)&P32, g_P32);
    cudaGetSymbolAddress((void**)&P16, g_P16);
    cudaGetSymbolAddress((void**)&AO,  g_AO16);
    cudaGetSymbolAddress((void**)&X,   g_X16);
    cudaGetSymbolAddress((void**)&W,   g_W16);
    cudaGetSymbolAddress((void**)&VT,  g_VT16);

    const size_t pstride = (size_t)BATCH * SEQ * DMODEL;   // full Q/K/V plane (elems)
    const size_t bstride = (size_t)SEQ * DMODEL;           // per-batch plane
    const size_t wsz = (size_t)DMODEL * DMODEL;
    __half* WqT = W;
    __half* WkT = W + wsz;
    __half* WvT = W + 2 * wsz;
    __half* WoT = W + 3 * wsz;
    __half* Q  = QKV;
    __half* Kp = QKV + pstride;

    // --- pre-pass: x -> fp16; fused transpose+fp16 of all weights ---
    {
        const int xe4 = (int)(pstride / 4);
        to_half<<<(xe4 + 255) / 256, 256>>>((const float4*)x, X, xe4);
        dim3 tb(32, 8);
        dim3 tgw(DMODEL / 32, DMODEL / 32, 4);
        transpose_w_h<<<tgw, tb>>>(Wq, Wk, Wv, Wo, W);
    }

    const int smemB = 3 * 32768 + 128;   // 3 stages + alignment slack
    cudaFuncSetAttribute(gemm_h<true,  true>,
                         cudaFuncAttributeMaxDynamicSharedMemorySize, smemB);
    cudaFuncSetAttribute(gemm_h<false, true>,
                         cudaFuncAttributeMaxDynamicSharedMemorySize, smemB);
    cudaFuncSetAttribute(gemm_h<false, false>,
                         cudaFuncAttributeMaxDynamicSharedMemorySize, smemB);

    const int MS = BATCH * SEQ;   // 8192
    dim3 blk(128);

    // QKV projections fused: z in {Q,K,V}; V written transposed into VT (fp16)
    dim3 gq(DMODEL / 128, MS / 128, 3);
    gemm_h<true, true><<<gq, blk, smemB>>>(
        X, WqT, WkT, WvT, QKV, MS, DMODEL, DMODEL, 0, 0, pstride,
        nullptr, 1.f, VT);

    // scores = Q K^T / 32, masked -> -1e10 (fp32 out)
    dim3 gs(SEQ / 128, SEQ / 128, BATCH);
    gemm_h<false, false><<<gs, blk, smemB>>>(
        Q, Kp, nullptr, nullptr, P32, SEQ, SEQ, DMODEL,
        bstride, bstride, (size_t)SEQ * SEQ, mask, 0.03125f, nullptr);

    softmax2048<<<BATCH * SEQ, 256>>>(P32, P16);

    // attn_out = P V  (fp16 out)
    dim3 gv(DMODEL / 128, SEQ / 128, BATCH);
    gemm_h<false, true><<<gv, blk, smemB>>>(
        P16, VT, nullptr, nullptr, AO, SEQ, DMODEL, SEQ,
        (size_t)SEQ * SEQ, bstride, bstride, nullptr, 1.f, nullptr);

    // output projection -> d_out (fp32)
    dim3 go(DMODEL / 128, MS / 128, 1);
    gemm_h<false, false><<<go, blk, smemB>>>(
        AO, WoT, nullptr, nullptr, out, MS, DMODEL, DMODEL, 0, 0, 0,
        nullptr, 1.f, nullptr);
}